// round 11
// baseline (speedup 1.0000x reference)
#include <cuda_runtime.h>
#include <cuda_fp16.h>
#include <cstdint>

// Based linear attention == causal attention with phi(s)=s+0.5*s^2, s=scale*(q.k).
// Warp-level mma.sync (fp16 m16n8k16, fp32 accum), single-rounded fp16 operands
// (calibrated rel_err ~4.3e-4 < 1e-3).
// R11: instruction diet — causal masking only on the diagonal (edge) tile via a
// uniform warp branch; LDSM pairing (p-step 2) to overlap ldmatrix latency with
// MMA issue; FFMA-imm form for phi. 64-row k-tiles, 4-stage cp.async ring,
// one barrier per iteration.

#define BB 2
#define HH 16
#define SEQ 2048
#define DD 64
#define QROWS 128
#define KROWS 64
#define NQT (SEQ / QROWS)   // 16
#define NBH (BB * HH)       // 32
#define TOTAL_ELEMS (NBH * SEQ * DD)
#define TOTAL_F4    (TOTAL_ELEMS / 4)

// fp16 K/V scratch (uint2 = 4 halfs), element order == original fp32 order
__device__ uint2 g_kh[TOTAL_F4];
__device__ uint2 g_vh[TOTAL_F4];

// 4-stage ring; stage = 64-row k-tile: KH 8KB | VH 8KB
#define STAGE_BYTES 16384
#define SOFF_KH 0
#define SOFF_VH 8192
#define NSTAGE 4
#define SMEM_TOTAL (NSTAGE * STAGE_BYTES)   // 65536

__device__ __forceinline__ uint32_t smem_u32(const void* p) {
    uint32_t a;
    asm("{ .reg .u64 t; cvta.to.shared.u64 t, %1; cvt.u32.u64 %0, t; }" : "=r"(a) : "l"(p));
    return a;
}

// byte swizzle for 128B rows: XOR row[2:0] into 16B-chunk index
__device__ __forceinline__ uint32_t swz(uint32_t b) { return b ^ ((b >> 3) & 0x70); }

__device__ __forceinline__ void mma_f16(float* c, uint32_t a0, uint32_t a1,
                                        uint32_t a2, uint32_t a3,
                                        uint32_t b0, uint32_t b1) {
    asm volatile(
        "mma.sync.aligned.m16n8k16.row.col.f32.f16.f16.f32 "
        "{%0,%1,%2,%3}, {%4,%5,%6,%7}, {%8,%9}, {%0,%1,%2,%3};"
        : "+f"(c[0]), "+f"(c[1]), "+f"(c[2]), "+f"(c[3])
        : "r"(a0), "r"(a1), "r"(a2), "r"(a3), "r"(b0), "r"(b1));
}

__device__ __forceinline__ void ldsm4(uint32_t* r, uint32_t addr) {
    asm volatile("ldmatrix.sync.aligned.m8n8.x4.shared.b16 {%0,%1,%2,%3}, [%4];"
                 : "=r"(r[0]), "=r"(r[1]), "=r"(r[2]), "=r"(r[3]) : "r"(addr));
}
__device__ __forceinline__ void ldsm4t(uint32_t* r, uint32_t addr) {
    asm volatile("ldmatrix.sync.aligned.m8n8.x4.trans.shared.b16 {%0,%1,%2,%3}, [%4];"
                 : "=r"(r[0]), "=r"(r[1]), "=r"(r[2]), "=r"(r[3]) : "r"(addr));
}

__device__ __forceinline__ void cp_async16(uint32_t smem_dst, const void* gptr) {
    asm volatile("cp.async.cg.shared.global [%0], [%1], 16;"
                 :: "r"(smem_dst), "l"(gptr) : "memory");
}
#define CP_COMMIT() asm volatile("cp.async.commit_group;" ::: "memory")
#define CP_WAIT2()  asm volatile("cp.async.wait_group 2;" ::: "memory")
#define CP_WAIT1()  asm volatile("cp.async.wait_group 1;" ::: "memory")
#define CP_WAIT0()  asm volatile("cp.async.wait_group 0;" ::: "memory")

// pack (x,y) into one half2 word
__device__ __forceinline__ uint32_t pack2h(float x, float y) {
    __half2 h = __floats2half2_rn(x, y);
    return *reinterpret_cast<uint32_t*>(&h);
}

// phi(s) = s * (1 + 0.5*s)  — FFMA-imm + FMUL
__device__ __forceinline__ float phi(float s) {
    return s * fmaf(s, 0.5f, 1.0f);
}

// ---- prepass: round K, V to fp16 scratch ----
__global__ __launch_bounds__(256)
void conv_kv_kernel(const float* __restrict__ k, const float* __restrict__ v) {
    int idx = blockIdx.x * 256 + threadIdx.x;     // float4 index
    float4 kv = reinterpret_cast<const float4*>(k)[idx];
    g_kh[idx] = make_uint2(pack2h(kv.x, kv.y), pack2h(kv.z, kv.w));
    float4 vv = reinterpret_cast<const float4*>(v)[idx];
    g_vh[idx] = make_uint2(pack2h(vv.x, vv.y), pack2h(vv.z, vv.w));
}

__global__ __launch_bounds__(256, 2)
void based_mma_kernel(const float* __restrict__ q, float* __restrict__ out)
{
    extern __shared__ char sm[];
    const uint32_t sbase = smem_u32(sm);

    const int tid  = threadIdx.x;
    const int lane = tid & 31;
    const int w    = tid >> 5;          // warp 0..7, owns q-rows [16w,16w+16)
    const int g    = lane >> 2;
    const int t4   = lane & 3;

    const int bh = blockIdx.y;
    const int qt = (NQT - 1) - blockIdx.x;   // big q-tiles first
    const size_t head = (size_t)bh * SEQ * DD;
    const size_t headB = head * 2;           // byte offset into g_* scratch
    const int nkt = 2 * qt + 2;              // 64-row k-tiles

    const char* khB = (const char*)g_kh + headB;
    const char* vhB = (const char*)g_vh + headB;

    // two 16B chunks per thread per 8KB sub-tile
    auto issue_tile = [&](int kt) {
        uint32_t sb = sbase + (kt & (NSTAGE - 1)) * STAGE_BYTES;
        size_t tb = (size_t)kt * 8192;    // 64*64*2 bytes per tile
        #pragma unroll
        for (int i = 0; i < 2; ++i) {
            int c = tid + i * 256;                 // chunk 0..511
            uint32_t so = swz((uint32_t)(c * 16));
            cp_async16(sb + SOFF_KH + so, khB + tb + c * 16);
            cp_async16(sb + SOFF_VH + so, vhB + tb + c * 16);
        }
        CP_COMMIT();
    };

    // ---- prologue: stage tiles 0,1 ----
    issue_tile(0);
    if (nkt > 1) issue_tile(1);

    // ---- Q fragments: register-resident single fp16 (overlaps the cp.asyncs) ----
    uint32_t qh[4][4];
    const int r0 = qt * QROWS + w * 16 + g;
    {
        const float scale = 0.125f;
        const float* qb = q + head;
        #pragma unroll
        for (int kb = 0; kb < 4; ++kb)
            #pragma unroll
            for (int h = 0; h < 4; ++h) {
                int row = r0 + ((h & 1) ? 8 : 0);
                int col = kb * 16 + t4 * 2 + ((h & 2) ? 8 : 0);
                float2 val = *reinterpret_cast<const float2*>(qb + (size_t)row * DD + col);
                qh[kb][h] = pack2h(val.x * scale, val.y * scale);
            }
    }

    float oacc[8][4] = {};

    const uint32_t sw = (lane & 7) << 4;
    const int rowK = ((lane >> 3) & 1) * 8 + (lane & 7);
    const int colK = (lane >> 4) * 16;
    const int rowV = ((lane >> 4) & 1) * 8 + (lane & 7);
    const int colV = ((lane >> 3) & 1) * 16;
    const int r0w  = qt * QROWS + w * 16;     // warp's first q-row

    for (int kt = 0; kt < nkt; ++kt) {
        // distance-2 prefetch; issue before wait; bounded tail waits.
        if (kt + 2 < nkt) { issue_tile(kt + 2); CP_WAIT2(); }
        else if (kt + 1 < nkt) { CP_WAIT1(); }
        else { CP_WAIT0(); }
        __syncthreads();   // tile kt visible to all warps

        if (kt * KROWS > r0w + 15) continue;   // fully masked for this warp

        const uint32_t sb = sbase + (kt & (NSTAGE - 1)) * STAGE_BYTES;
        const uint32_t kh_b = sb + SOFF_KH, vh_b = sb + SOFF_VH;

        // ---- GEMM1: S[16x64] = Q_h * K_h^T  (paired LDSM, 8 acc chains) ----
        float sacc[8][4] = {};
        #pragma unroll
        for (int kk = 0; kk < 4; ++kk) {
            #pragma unroll
            for (int p = 0; p < 4; p += 2) {
                uint32_t off0 = (uint32_t)((16 * p + rowK) * 128)      + (((uint32_t)(32 * kk + colK)) ^ sw);
                uint32_t off1 = (uint32_t)((16 * (p+1) + rowK) * 128)  + (((uint32_t)(32 * kk + colK)) ^ sw);
                uint32_t br0[4], br1[4];
                ldsm4(br0, kh_b + off0);
                ldsm4(br1, kh_b + off1);
                mma_f16(sacc[2*p],   qh[kk][0],qh[kk][1],qh[kk][2],qh[kk][3], br0[0], br0[2]);
                mma_f16(sacc[2*p+1], qh[kk][0],qh[kk][1],qh[kk][2],qh[kk][3], br0[1], br0[3]);
                mma_f16(sacc[2*p+2], qh[kk][0],qh[kk][1],qh[kk][2],qh[kk][3], br1[0], br1[2]);
                mma_f16(sacc[2*p+3], qh[kk][0],qh[kk][1],qh[kk][2],qh[kk][3], br1[1], br1[3]);
            }
        }

        // ---- phi + GEMM2; causal mask only on the (uniform) edge tile ----
        const bool edge = (kt * KROWS + KROWS - 1 > r0w);
        if (!edge) {
            // fast path: no masking at all
            #pragma unroll
            for (int kk2 = 0; kk2 < 4; ++kk2) {
                uint32_t ah[4];
                #pragma unroll
                for (int half = 0; half < 2; ++half) {
                    int nb = 2 * kk2 + half;
                    ah[2*half]     = pack2h(phi(sacc[nb][0]), phi(sacc[nb][1]));
                    ah[2*half + 1] = pack2h(phi(sacc[nb][2]), phi(sacc[nb][3]));
                }
                #pragma unroll
                for (int p = 0; p < 4; p += 2) {
                    uint32_t off0 = (uint32_t)((16 * kk2 + rowV) * 128) + (((uint32_t)(32 * p + colV)) ^ sw);
                    uint32_t off1 = (uint32_t)((16 * kk2 + rowV) * 128) + (((uint32_t)(32 * (p+1) + colV)) ^ sw);
                    uint32_t vr0[4], vr1[4];
                    ldsm4t(vr0, vh_b + off0);
                    ldsm4t(vr1, vh_b + off1);
                    mma_f16(oacc[2*p],   ah[0],ah[1],ah[2],ah[3], vr0[0], vr0[2]);
                    mma_f16(oacc[2*p+1], ah[0],ah[1],ah[2],ah[3], vr0[1], vr0[3]);
                    mma_f16(oacc[2*p+2], ah[0],ah[1],ah[2],ah[3], vr1[0], vr1[2]);
                    mma_f16(oacc[2*p+3], ah[0],ah[1],ah[2],ah[3], vr1[1], vr1[3]);
                }
            }
        } else {
            // edge path: apply causal mask before phi
            #pragma unroll
            for (int kk2 = 0; kk2 < 4; ++kk2) {
                uint32_t ah[4];
                #pragma unroll
                for (int half = 0; half < 2; ++half) {
                    int nb = 2 * kk2 + half;
                    int colg = kt * KROWS + nb * 8 + 2 * t4;
                    float e[4];
                    #pragma unroll
                    for (int u = 0; u < 4; ++u) {
                        float p = phi(sacc[nb][u]);
                        if (colg + (u & 1) > r0 + ((u & 2) ? 8 : 0)) p = 0.0f;
                        e[u] = p;
                    }
                    ah[2*half]     = pack2h(e[0], e[1]);
                    ah[2*half + 1] = pack2h(e[2], e[3]);
                }
                #pragma unroll
                for (int p = 0; p < 4; p += 2) {
                    uint32_t off0 = (uint32_t)((16 * kk2 + rowV) * 128) + (((uint32_t)(32 * p + colV)) ^ sw);
                    uint32_t off1 = (uint32_t)((16 * kk2 + rowV) * 128) + (((uint32_t)(32 * (p+1) + colV)) ^ sw);
                    uint32_t vr0[4], vr1[4];
                    ldsm4t(vr0, vh_b + off0);
                    ldsm4t(vr1, vh_b + off1);
                    mma_f16(oacc[2*p],   ah[0],ah[1],ah[2],ah[3], vr0[0], vr0[2]);
                    mma_f16(oacc[2*p+1], ah[0],ah[1],ah[2],ah[3], vr0[1], vr0[3]);
                    mma_f16(oacc[2*p+2], ah[0],ah[1],ah[2],ah[3], vr1[0], vr1[2]);
                    mma_f16(oacc[2*p+3], ah[0],ah[1],ah[2],ah[3], vr1[1], vr1[3]);
                }
            }
        }
    }

    // ---- store O fragments ----
    float* og = out + head;
    #pragma unroll
    for (int nb = 0; nb < 8; ++nb) {
        int col = nb * 8 + 2 * t4;
        *reinterpret_cast<float2*>(og + (size_t)r0 * DD + col) =
            make_float2(oacc[nb][0], oacc[nb][1]);
        *reinterpret_cast<float2*>(og + (size_t)(r0 + 8) * DD + col) =
            make_float2(oacc[nb][2], oacc[nb][3]);
    }
}

extern "C" void kernel_launch(void* const* d_in, const int* in_sizes, int n_in,
                              void* d_out, int out_size) {
    const float* q = (const float*)d_in[0];
    const float* k = (const float*)d_in[1];
    const float* v = (const float*)d_in[2];
    float* out = (float*)d_out;

    static bool attr_set = false;
    if (!attr_set) {
        cudaFuncSetAttribute(based_mma_kernel,
                             cudaFuncAttributeMaxDynamicSharedMemorySize, SMEM_TOTAL);
        attr_set = true;
    }

    conv_kv_kernel<<<TOTAL_F4 / 256, 256>>>(k, v);
    dim3 grid(NQT, NBH);
    based_mma_kernel<<<grid, 256, SMEM_TOTAL>>>(q, out);
}

// round 13
// speedup vs baseline: 1.0737x; 1.0737x over previous
#include <cuda_runtime.h>
#include <cuda_fp16.h>
#include <cstdint>

// Based linear attention == causal attention with phi(s)=s+0.5*s^2, s=scale*(q.k).
// Warp-level mma.sync (fp16 m16n8k16, fp32 accum), single-rounded fp16 operands
// (calibrated rel_err ~4.3e-4 < 1e-3).
// R13: R12 (128-thread CTAs, QROWS=64, 3-stage ring, 4 CTAs/SM) with the ring
// RACE FIXED: tile kt+2 is issued AFTER the barrier of iteration kt, so the
// overwritten stage (== tile kt-1's) has no readers left. Uniform CP_WAIT1 at
// the loop top (one newer group pending), CP_WAIT0 on the last tile.

#define BB 2
#define HH 16
#define SEQ 2048
#define DD 64
#define QROWS 64
#define KROWS 64
#define NQT (SEQ / QROWS)   // 32
#define NBH (BB * HH)       // 32
#define TOTAL_ELEMS (NBH * SEQ * DD)
#define TOTAL_F4    (TOTAL_ELEMS / 4)

// fp16 K/V scratch (uint2 = 4 halfs), element order == original fp32 order
__device__ uint2 g_kh[TOTAL_F4];
__device__ uint2 g_vh[TOTAL_F4];

// 3-stage ring; stage = 64-row k-tile: KH 8KB | VH 8KB
#define STAGE_BYTES 16384
#define SOFF_KH 0
#define SOFF_VH 8192
#define NSTAGE 3
#define SMEM_TOTAL (NSTAGE * STAGE_BYTES)   // 49152

__device__ __forceinline__ uint32_t smem_u32(const void* p) {
    uint32_t a;
    asm("{ .reg .u64 t; cvta.to.shared.u64 t, %1; cvt.u32.u64 %0, t; }" : "=r"(a) : "l"(p));
    return a;
}

// byte swizzle for 128B rows: XOR row[2:0] into 16B-chunk index
__device__ __forceinline__ uint32_t swz(uint32_t b) { return b ^ ((b >> 3) & 0x70); }

__device__ __forceinline__ void mma_f16(float* c, uint32_t a0, uint32_t a1,
                                        uint32_t a2, uint32_t a3,
                                        uint32_t b0, uint32_t b1) {
    asm volatile(
        "mma.sync.aligned.m16n8k16.row.col.f32.f16.f16.f32 "
        "{%0,%1,%2,%3}, {%4,%5,%6,%7}, {%8,%9}, {%0,%1,%2,%3};"
        : "+f"(c[0]), "+f"(c[1]), "+f"(c[2]), "+f"(c[3])
        : "r"(a0), "r"(a1), "r"(a2), "r"(a3), "r"(b0), "r"(b1));
}

__device__ __forceinline__ void ldsm4(uint32_t* r, uint32_t addr) {
    asm volatile("ldmatrix.sync.aligned.m8n8.x4.shared.b16 {%0,%1,%2,%3}, [%4];"
                 : "=r"(r[0]), "=r"(r[1]), "=r"(r[2]), "=r"(r[3]) : "r"(addr));
}
__device__ __forceinline__ void ldsm4t(uint32_t* r, uint32_t addr) {
    asm volatile("ldmatrix.sync.aligned.m8n8.x4.trans.shared.b16 {%0,%1,%2,%3}, [%4];"
                 : "=r"(r[0]), "=r"(r[1]), "=r"(r[2]), "=r"(r[3]) : "r"(addr));
}

__device__ __forceinline__ void cp_async16(uint32_t smem_dst, const void* gptr) {
    asm volatile("cp.async.cg.shared.global [%0], [%1], 16;"
                 :: "r"(smem_dst), "l"(gptr) : "memory");
}
#define CP_COMMIT() asm volatile("cp.async.commit_group;" ::: "memory")
#define CP_WAIT1()  asm volatile("cp.async.wait_group 1;" ::: "memory")
#define CP_WAIT0()  asm volatile("cp.async.wait_group 0;" ::: "memory")

// pack (x,y) into one half2 word
__device__ __forceinline__ uint32_t pack2h(float x, float y) {
    __half2 h = __floats2half2_rn(x, y);
    return *reinterpret_cast<uint32_t*>(&h);
}

// ---- prepass: round K, V to fp16 scratch ----
__global__ __launch_bounds__(256)
void conv_kv_kernel(const float* __restrict__ k, const float* __restrict__ v) {
    int idx = blockIdx.x * 256 + threadIdx.x;     // float4 index
    float4 kv = reinterpret_cast<const float4*>(k)[idx];
    g_kh[idx] = make_uint2(pack2h(kv.x, kv.y), pack2h(kv.z, kv.w));
    float4 vv = reinterpret_cast<const float4*>(v)[idx];
    g_vh[idx] = make_uint2(pack2h(vv.x, vv.y), pack2h(vv.z, vv.w));
}

__global__ __launch_bounds__(128, 4)
void based_mma_kernel(const float* __restrict__ q, float* __restrict__ out)
{
    extern __shared__ char sm[];
    const uint32_t sbase = smem_u32(sm);

    const int tid  = threadIdx.x;
    const int lane = tid & 31;
    const int w    = tid >> 5;          // warp 0..3, owns q-rows [16w,16w+16)
    const int g    = lane >> 2;
    const int t4   = lane & 3;

    const int bh = blockIdx.y;
    const int qt = (NQT - 1) - blockIdx.x;   // big q-tiles first
    const size_t head = (size_t)bh * SEQ * DD;
    const size_t headB = head * 2;           // byte offset into g_* scratch
    const int nkt = qt + 1;                  // 64-row k-tiles, causal

    const char* khB = (const char*)g_kh + headB;
    const char* vhB = (const char*)g_vh + headB;

    // four 16B chunks per thread per 8KB sub-tile
    auto issue_tile = [&](int kt) {
        uint32_t sb = sbase + (kt % NSTAGE) * STAGE_BYTES;
        size_t tb = (size_t)kt * 8192;    // 64*64*2 bytes per tile
        #pragma unroll
        for (int i = 0; i < 4; ++i) {
            int c = tid + i * 128;                 // chunk 0..511
            uint32_t so = swz((uint32_t)(c * 16));
            cp_async16(sb + SOFF_KH + so, khB + tb + c * 16);
            cp_async16(sb + SOFF_VH + so, vhB + tb + c * 16);
        }
        CP_COMMIT();
    };

    // ---- prologue: stage tiles 0,1 ----
    issue_tile(0);
    if (nkt > 1) issue_tile(1);

    // ---- Q fragments: register-resident single fp16 (overlaps the cp.asyncs) ----
    uint32_t qh[4][4];
    const int r0 = qt * QROWS + w * 16 + g;
    {
        const float scale = 0.125f;
        const float* qb = q + head;
        #pragma unroll
        for (int kb = 0; kb < 4; ++kb)
            #pragma unroll
            for (int h = 0; h < 4; ++h) {
                int row = r0 + ((h & 1) ? 8 : 0);
                int col = kb * 16 + t4 * 2 + ((h & 2) ? 8 : 0);
                float2 val = *reinterpret_cast<const float2*>(qb + (size_t)row * DD + col);
                qh[kb][h] = pack2h(val.x * scale, val.y * scale);
            }
    }

    float oacc[8][4] = {};

    const uint32_t sw = (lane & 7) << 4;
    const int rowK = ((lane >> 3) & 1) * 8 + (lane & 7);
    const int colK = (lane >> 4) * 16;
    const int rowV = ((lane >> 4) & 1) * 8 + (lane & 7);
    const int colV = ((lane >> 3) & 1) * 16;
    const int r0w  = qt * QROWS + w * 16;     // warp's first q-row

    for (int kt = 0; kt < nkt; ++kt) {
        // At loop top exactly one newer group (tile kt+1) may be pending.
        if (kt + 1 < nkt) { CP_WAIT1(); } else { CP_WAIT0(); }
        __syncthreads();   // tile kt visible to all warps; readers of tile
                           // kt-1 (stage (kt+2)%3) are ALL done past this point.

        // Issue tile kt+2 only now — its stage belonged to tile kt-1.
        if (kt + 2 < nkt) issue_tile(kt + 2);

        const uint32_t sb = sbase + (kt % NSTAGE) * STAGE_BYTES;
        const uint32_t kh_b = sb + SOFF_KH, vh_b = sb + SOFF_VH;

        // ---- GEMM1: S[16x64] = Q_h * K_h^T  (8 independent acc chains) ----
        float sacc[8][4] = {};
        #pragma unroll
        for (int kk = 0; kk < 4; ++kk) {
            #pragma unroll
            for (int p = 0; p < 4; ++p) {
                uint32_t off = (uint32_t)((16 * p + rowK) * 128) + (((uint32_t)(32 * kk + colK)) ^ sw);
                uint32_t br[4];
                ldsm4(br, kh_b + off);
                mma_f16(sacc[2*p],   qh[kk][0],qh[kk][1],qh[kk][2],qh[kk][3], br[0], br[2]);
                mma_f16(sacc[2*p+1], qh[kk][0],qh[kk][1],qh[kk][2],qh[kk][3], br[1], br[3]);
            }
        }

        // ---- phi + GEMM2 interleaved per k-step: O += phi_h * V_h ----
        const bool edge = (kt * KROWS + KROWS - 1 > r0w);
        #pragma unroll
        for (int kk2 = 0; kk2 < 4; ++kk2) {
            uint32_t ah[4];
            #pragma unroll
            for (int half = 0; half < 2; ++half) {        // nb = 2*kk2+half
                int nb = 2 * kk2 + half;
                int colg = kt * KROWS + nb * 8 + 2 * t4;
                float e[4];
                #pragma unroll
                for (int u = 0; u < 4; ++u) {
                    float s = sacc[nb][u];
                    float p = fmaf(0.5f * s, s, s);
                    if (edge && (colg + (u & 1) > r0 + ((u & 2) ? 8 : 0))) p = 0.0f;
                    e[u] = p;
                }
                ah[2*half]     = pack2h(e[0], e[1]);
                ah[2*half + 1] = pack2h(e[2], e[3]);
            }
            #pragma unroll
            for (int p = 0; p < 4; ++p) {
                uint32_t off = (uint32_t)((16 * kk2 + rowV) * 128) + (((uint32_t)(32 * p + colV)) ^ sw);
                uint32_t vr[4];
                ldsm4t(vr, vh_b + off);
                mma_f16(oacc[2*p],   ah[0],ah[1],ah[2],ah[3], vr[0], vr[2]);
                mma_f16(oacc[2*p+1], ah[0],ah[1],ah[2],ah[3], vr[1], vr[3]);
            }
        }
    }

    // ---- store O fragments ----
    float* og = out + head;
    #pragma unroll
    for (int nb = 0; nb < 8; ++nb) {
        int col = nb * 8 + 2 * t4;
        *reinterpret_cast<float2*>(og + (size_t)r0 * DD + col) =
            make_float2(oacc[nb][0], oacc[nb][1]);
        *reinterpret_cast<float2*>(og + (size_t)(r0 + 8) * DD + col) =
            make_float2(oacc[nb][2], oacc[nb][3]);
    }
}

extern "C" void kernel_launch(void* const* d_in, const int* in_sizes, int n_in,
                              void* d_out, int out_size) {
    const float* q = (const float*)d_in[0];
    const float* k = (const float*)d_in[1];
    const float* v = (const float*)d_in[2];
    float* out = (float*)d_out;

    static bool attr_set = false;
    if (!attr_set) {
        cudaFuncSetAttribute(based_mma_kernel,
                             cudaFuncAttributeMaxDynamicSharedMemorySize, SMEM_TOTAL);
        attr_set = true;
    }

    conv_kv_kernel<<<TOTAL_F4 / 256, 256>>>(k, v);
    dim3 grid(NQT, NBH);
    based_mma_kernel<<<grid, 128, SMEM_TOTAL>>>(q, out);
}